// round 16
// baseline (speedup 1.0000x reference)
#include <cuda_runtime.h>
#include <math.h>
#include <float.h>
#include <stdint.h>

#define BB 16
#define DD 512
#define TT 2048
#define NQ 9
#define CS 1024
#define CD 8
#define TTILE 64
#define NTHREADS 512
#define RESP 516   // res row pitch (floats): 516/4=129 ≡ 1 mod 32 -> conflict-free float4 rows

typedef unsigned long long ull;

__device__ __forceinline__ ull pk2(float lo, float hi) {
    ull r; asm("mov.b64 %0,{%1,%2};" : "=l"(r) : "f"(lo), "f"(hi)); return r;
}
__device__ __forceinline__ void upk2(float& lo, float& hi, ull v) {
    asm("mov.b64 {%0,%1},%2;" : "=f"(lo), "=f"(hi) : "l"(v));
}
__device__ __forceinline__ ull fma2(ull a, ull b, ull c) {
    ull d; asm("fma.rn.f32x2 %0,%1,%2,%3;" : "=l"(d) : "l"(a), "l"(b), "l"(c)); return d;
}
__device__ __forceinline__ ull mul2(ull a, ull b) {
    ull d; asm("mul.rn.f32x2 %0,%1,%2;" : "=l"(d) : "l"(a), "l"(b)); return d;
}

// ---------------- precomputed (normalized) parameter scratch ----------------
__device__ float g_win[NQ * CD * DD];    // weight-normed in_proj, c-major (q=0 standalone)
__device__ float g_winT[NQ * DD * CD];   // weight-normed in_proj, d-major (fused path)
__device__ float g_woutT[NQ * CD * DD];  // weight-normed out_proj TRANSPOSED (q, c, d)
__device__ float g_cbn[NQ * CS * CD];    // l2-normalized codebook (linear layout)
__device__ float g_csq[NQ * CS];         // sum(c_norm^2) per code

__global__ void rvq_precompute(const float* __restrict__ iv, const float* __restrict__ ig,
                               const float* __restrict__ ov, const float* __restrict__ og,
                               const float* __restrict__ cb) {
    int q = blockIdx.x;
    int tid = threadIdx.x;           // 256 threads
    int wid = tid >> 5, lane = tid & 31;

    if (wid < CD) {
        int c = wid;
        const float* v = iv + ((size_t)q * CD + c) * DD;
        float ss = 0.f;
        for (int d = lane; d < DD; d += 32) { float x = v[d]; ss = fmaf(x, x, ss); }
        #pragma unroll
        for (int o = 16; o > 0; o >>= 1) ss += __shfl_xor_sync(0xffffffffu, ss, o);
        float nrm = __fsqrt_rn(ss);
        float g = ig[q * CD + c];
        for (int d = lane; d < DD; d += 32) {
            float w = __fdiv_rn(g * v[d], nrm);
            g_win[((size_t)q * CD + c) * DD + d] = w;
            g_winT[((size_t)q * DD + d) * CD + c] = w;
        }
    }
    for (int r = tid; r < DD; r += 256) {
        const float* v = ov + ((size_t)q * DD + r) * CD;
        float ss = 0.f;
        #pragma unroll
        for (int c = 0; c < CD; c++) { float x = v[c]; ss = fmaf(x, x, ss); }
        float nrm = __fsqrt_rn(ss);
        float g = og[q * DD + r];
        #pragma unroll
        for (int c = 0; c < CD; c++)
            g_woutT[((size_t)q * CD + c) * DD + r] = __fdiv_rn(g * v[c], nrm);
    }
    for (int s = tid; s < CS; s += 256) {
        const float* v = cb + ((size_t)q * CS + s) * CD;
        float ss = 0.f;
        #pragma unroll
        for (int c = 0; c < CD; c++) { float x = v[c]; ss = fmaf(x, x, ss); }
        float den = fmaxf(__fsqrt_rn(ss), 1e-12f);
        float cs2 = 0.f;
        #pragma unroll
        for (int c = 0; c < CD; c++) {
            float cn = __fdiv_rn(v[c], den);
            g_cbn[((size_t)q * CS + s) * CD + c] = cn;
            cs2 = fmaf(cn, cn, cs2);
        }
        g_csq[q * CS + s] = cs2;
    }
}

// ---------------- async copy helpers ----------------
__device__ __forceinline__ void cp16(void* dst, const void* src) {
    uint32_t d = (uint32_t)__cvta_generic_to_shared(dst);
    asm volatile("cp.async.cg.shared.global [%0], [%1], 16;" :: "r"(d), "l"(src));
}
__device__ __forceinline__ void cp_commit() {
    asm volatile("cp.async.commit_group;" ::: "memory");
}
__device__ __forceinline__ void cp_wait0() {
    asm volatile("cp.async.wait_group 0;" ::: "memory");
}
__device__ __forceinline__ void cp_wait1() {
    asm volatile("cp.async.wait_group 1;" ::: "memory");
}

// ---------------- main fused RVQ kernel ----------------
struct SMem {
    float4 cbn4[CS * 2];          // 32768  normalized codebook (async group C)
    float  res[TTILE][RESP];      // 132096 residual tile, TRANSPOSED [t][d], pitch 516
    float4 winTn[DD * 2];         // 16384  next-q in_proj, d-major (async group W)
    float  woutT[CD * DD];        // 16384  out_proj c-major (async group W; pre-loop: win[0])
    float4 csq4[CS / 4];          // 4096   (async group C)
    float  ob[DD];                // 2048   (async group W)
    float  zi[CD][TTILE];         // 2048
    float  zqs[CD][TTILE];        // 2048
    union {                       // 16384 (disjoint windows: NN->z_q vs z_o->reduce)
        float2 red[16][TTILE];    // (dist, idx-as-float) per chunk
        float  part[CD][8][TTILE];
    } u;
    float ib_all[NQ * CD];        // 288
};  // ~224.5 KB

// packed out-projection for 4 consecutive d (bit-identical per-lane chain)
__device__ __forceinline__ void outproj4(const ulonglong2* wt, int wi,
                                         const ull* qq, ull& a01, ull& a23) {
    ulonglong2 wc = wt[wi];
    a01 = mul2(qq[0], wc.x);  a23 = mul2(qq[0], wc.y);
    #pragma unroll
    for (int c = 1; c < CD; c++) {
        wc = wt[c * (DD / 4) + wi];
        a01 = fma2(qq[c], wc.x, a01);
        a23 = fma2(qq[c], wc.y, a23);
    }
}

__global__ void __launch_bounds__(NTHREADS, 1)
rvq_kernel(const float* __restrict__ z,
           const float* __restrict__ ib_g,
           const float* __restrict__ ob_g,
           const float* __restrict__ cbraw,
           float* __restrict__ out) {
    extern __shared__ unsigned char smraw[];
    SMem& sm = *reinterpret_cast<SMem*>(smraw);

    const int tid = threadIdx.x;
    const int b = blockIdx.y;
    const int t0 = blockIdx.x * TTILE;

    float* out_codes = out;
    float* out_zO  = out + (size_t)BB * NQ * TT;
    float* out_zis = out_zO + (size_t)BB * DD * TT;
    float* out_zqs = out_zis + (size_t)BB * NQ * CD * TT;
    float* out_zos = out_zqs + (size_t)BB * NQ * CD * TT;

    // ---- async prefetch: group Wpre = win[0]; group C0 = cbn/csq(q=0) ----
    {
        const float4* s1 = reinterpret_cast<const float4*>(g_win);
        float4* d1 = reinterpret_cast<float4*>(&sm.woutT[0]);
        for (int i = tid; i < CD * DD / 4; i += NTHREADS) cp16(&d1[i], &s1[i]);
        cp_commit();   // group Wpre
        const float4* s3 = reinterpret_cast<const float4*>(g_cbn);
        for (int i = tid; i < CS * 2; i += NTHREADS) cp16(&sm.cbn4[i], &s3[i]);
        const float4* s4 = reinterpret_cast<const float4*>(g_csq);
        for (int i = tid; i < CS / 4; i += NTHREADS) cp16(&sm.csq4[i], &s4[i]);
        cp_commit();   // group C0 (lands by loop-top cp_wait0)
    }

    // ---- load residual tile TRANSPOSED into res[t][d] (sync) ----
    const float* zb = z + (size_t)b * DD * TT + t0;
    for (int f = tid; f < DD * (TTILE / 4); f += NTHREADS) {
        int d = f >> 4, j = f & 15;
        float4 v = reinterpret_cast<const float4*>(zb + (size_t)d * TT)[j];
        int tt = 4 * j;
        sm.res[tt + 0][d] = v.x;
        sm.res[tt + 1][d] = v.y;
        sm.res[tt + 2][d] = v.z;
        sm.res[tt + 3][d] = v.w;
    }
    if (tid < NQ * CD) sm.ib_all[tid] = ib_g[tid];
    cp_wait1();        // Wpre (win0) landed; C0 still in flight
    __syncthreads();

    const int t  = tid & (TTILE - 1);   // 0..63
    const int hi = tid >> 6;            // 0..7 (c / d-group)
    const int ch = tid >> 5;            // 0..15 NN chunk of 64 codes
    const int tp = tid & 31;            // NN t-pair: t = 2tp, 2tp+1

    // ---- standalone z_i for q=0  (thread = (c=hi, t)) ----
    {
        const float4* wr4 = reinterpret_cast<const float4*>(&sm.woutT[hi * DD]);
        const float4* rr4 = reinterpret_cast<const float4*>(&sm.res[t][0]);
        float a0 = 0.f, a1 = 0.f, a2 = 0.f, a3 = 0.f;
        #pragma unroll 4
        for (int i = 0; i < DD / 4; i++) {
            float4 w = wr4[i];
            float4 r = rr4[i];
            a0 = fmaf(w.x, r.x, a0);
            a1 = fmaf(w.y, r.y, a1);
            a2 = fmaf(w.z, r.z, a2);
            a3 = fmaf(w.w, r.w, a3);
        }
        float ziv = ((a0 + a1) + (a2 + a3)) + sm.ib_all[hi];
        sm.zi[hi][t] = ziv;
        out_zis[(((size_t)b * NQ + 0) * CD + hi) * TT + t0 + t] = ziv;
    }

    for (int q = 0; q < NQ; q++) {
        cp_wait0();        // C group (codebook for this q) landed
        __syncthreads();   // zi ready; prev z_o table reads done; prefetch visible

        // ---- async stage group W: woutT(q), ob(q), winT(q+1) — waited before z_o ----
        {
            const float4* s2 = reinterpret_cast<const float4*>(g_woutT + (size_t)q * CD * DD);
            float4* d2 = reinterpret_cast<float4*>(&sm.woutT[0]);
            for (int i = tid; i < CD * DD / 4; i += NTHREADS) cp16(&d2[i], &s2[i]);
            const float4* s5 = reinterpret_cast<const float4*>(ob_g + (size_t)q * DD);
            float4* d5 = reinterpret_cast<float4*>(&sm.ob[0]);
            for (int i = tid; i < DD / 4; i += NTHREADS) cp16(&d5[i], &s5[i]);
            if (q < NQ - 1) {
                const float4* s6 = reinterpret_cast<const float4*>(
                    g_winT + (size_t)(q + 1) * DD * CD);
                for (int i = tid; i < DD * 2; i += NTHREADS) cp16(&sm.winTn[i], &s6[i]);
            }
            cp_commit();   // group W
        }

        // ---- NN search: thread = (chunk ch of 64 codes, 2 t-columns) ----
        {
            const int ta = 2 * tp, tb = 2 * tp + 1;
            float za0 = sm.zi[0][ta], za1 = sm.zi[1][ta], za2 = sm.zi[2][ta], za3 = sm.zi[3][ta];
            float za4 = sm.zi[4][ta], za5 = sm.zi[5][ta], za6 = sm.zi[6][ta], za7 = sm.zi[7][ta];
            float zb0 = sm.zi[0][tb], zb1 = sm.zi[1][tb], zb2 = sm.zi[2][tb], zb3 = sm.zi[3][tb];
            float zb4 = sm.zi[4][tb], zb5 = sm.zi[5][tb], zb6 = sm.zi[6][tb], zb7 = sm.zi[7][tb];
            float sa = za0 * za0;
            sa = fmaf(za1, za1, sa); sa = fmaf(za2, za2, sa); sa = fmaf(za3, za3, sa);
            sa = fmaf(za4, za4, sa); sa = fmaf(za5, za5, sa); sa = fmaf(za6, za6, sa);
            sa = fmaf(za7, za7, sa);
            float sb = zb0 * zb0;
            sb = fmaf(zb1, zb1, sb); sb = fmaf(zb2, zb2, sb); sb = fmaf(zb3, zb3, sb);
            sb = fmaf(zb4, zb4, sb); sb = fmaf(zb5, zb5, sb); sb = fmaf(zb6, zb6, sb);
            sb = fmaf(zb7, zb7, sb);
            float dena = fmaxf(__fsqrt_rn(sa), 1e-12f);
            float denb = fmaxf(__fsqrt_rn(sb), 1e-12f);
            float ea0 = __fdiv_rn(za0, dena), ea1 = __fdiv_rn(za1, dena);
            float ea2 = __fdiv_rn(za2, dena), ea3 = __fdiv_rn(za3, dena);
            float ea4 = __fdiv_rn(za4, dena), ea5 = __fdiv_rn(za5, dena);
            float ea6 = __fdiv_rn(za6, dena), ea7 = __fdiv_rn(za7, dena);
            float eb0 = __fdiv_rn(zb0, denb), eb1 = __fdiv_rn(zb1, denb);
            float eb2 = __fdiv_rn(zb2, denb), eb3 = __fdiv_rn(zb3, denb);
            float eb4 = __fdiv_rn(zb4, denb), eb5 = __fdiv_rn(zb5, denb);
            float eb6 = __fdiv_rn(zb6, denb), eb7 = __fdiv_rn(zb7, denb);
            float eqa = ea0 * ea0;
            eqa = fmaf(ea1, ea1, eqa); eqa = fmaf(ea2, ea2, eqa); eqa = fmaf(ea3, ea3, eqa);
            eqa = fmaf(ea4, ea4, eqa); eqa = fmaf(ea5, ea5, eqa); eqa = fmaf(ea6, ea6, eqa);
            eqa = fmaf(ea7, ea7, eqa);
            float eqb = eb0 * eb0;
            eqb = fmaf(eb1, eb1, eqb); eqb = fmaf(eb2, eb2, eqb); eqb = fmaf(eb3, eb3, eqb);
            eqb = fmaf(eb4, eb4, eqb); eqb = fmaf(eb5, eb5, eqb); eqb = fmaf(eb6, eb6, eqb);
            eqb = fmaf(eb7, eb7, eqb);

            // channel-pair packed encodings (tree-sum dot; rounding validated R2/R14)
            ull pa0 = pk2(ea0, ea1), pa1 = pk2(ea2, ea3);
            ull pa2 = pk2(ea4, ea5), pa3 = pk2(ea6, ea7);
            ull pb0 = pk2(eb0, eb1), pb1 = pk2(eb2, eb3);
            ull pb2 = pk2(eb4, eb5), pb3 = pk2(eb6, eb7);

            const ulonglong2* cbp = reinterpret_cast<const ulonglong2*>(sm.cbn4);
            const float* csqs = reinterpret_cast<const float*>(sm.csq4);
            const int s0 = ch * 64;
            float bA0 = FLT_MAX, bA1 = FLT_MAX, bB0 = FLT_MAX, bB1 = FLT_MAX;
            int   iA0 = 0, iA1 = 0, iB0 = 0, iB1 = 0;
            #pragma unroll 4
            for (int s = s0; s < s0 + 64; s += 2) {
                ulonglong2 uA0 = cbp[2 * s],     uA1 = cbp[2 * s + 1];
                ulonglong2 uB0 = cbp[2 * s + 2], uB1 = cbp[2 * s + 3];
                float2 csv = *reinterpret_cast<const float2*>(csqs + s);
                ull tAa = fma2(pa0, uA0.x, fma2(pa1, uA0.y, fma2(pa2, uA1.x, mul2(pa3, uA1.y))));
                ull tAb = fma2(pb0, uA0.x, fma2(pb1, uA0.y, fma2(pb2, uA1.x, mul2(pb3, uA1.y))));
                ull tBa = fma2(pa0, uB0.x, fma2(pa1, uB0.y, fma2(pa2, uB1.x, mul2(pa3, uB1.y))));
                ull tBb = fma2(pb0, uB0.x, fma2(pb1, uB0.y, fma2(pb2, uB1.x, mul2(pb3, uB1.y))));
                float lo, hi2;
                upk2(lo, hi2, tAa); float dAa = fmaf(-2.0f, lo + hi2, eqa) + csv.x;
                upk2(lo, hi2, tAb); float dAb = fmaf(-2.0f, lo + hi2, eqb) + csv.x;
                upk2(lo, hi2, tBa); float dBa = fmaf(-2.0f, lo + hi2, eqa) + csv.y;
                upk2(lo, hi2, tBb); float dBb = fmaf(-2.0f, lo + hi2, eqb) + csv.y;
                if (dAa < bA0) { bA0 = dAa; iA0 = s; }
                if (dAb < bA1) { bA1 = dAb; iA1 = s; }
                if (dBa < bB0) { bB0 = dBa; iB0 = s + 1; }
                if (dBb < bB1) { bB1 = dBb; iB1 = s + 1; }
            }
            // merge even/odd chains, exact first-index tie-break
            if (bB0 < bA0 || (bB0 == bA0 && iB0 < iA0)) { bA0 = bB0; iA0 = iB0; }
            if (bB1 < bA1 || (bB1 == bA1 && iB1 < iA1)) { bA1 = bB1; iA1 = iB1; }
            sm.u.red[ch][ta] = make_float2(bA0, (float)iA0);
            sm.u.red[ch][tb] = make_float2(bA1, (float)iA1);
        }
        __syncthreads();

        // ---- issue group C: prefetch next-q codebook (flies through z_q + z_o) ----
        if (q < NQ - 1) {
            const float4* srcC = reinterpret_cast<const float4*>(
                g_cbn + (size_t)(q + 1) * CS * CD);
            for (int i = tid; i < CS * 2; i += NTHREADS) cp16(&sm.cbn4[i], &srcC[i]);
            const float4* srcQ = reinterpret_cast<const float4*>(
                g_csq + (size_t)(q + 1) * CS);
            for (int i = tid; i < CS / 4; i += NTHREADS) cp16(&sm.csq4[i], &srcQ[i]);
            cp_commit();   // group C
        }

        // ---- z_q: redundant argmin merge (16 chunks) + straight-through (c=hi, t) ----
        {
            float2 v0 = sm.u.red[0][t];
            float bb = v0.x; float bif = v0.y;
            #pragma unroll
            for (int g = 1; g < 16; g++) {
                float2 v = sm.u.red[g][t];
                if (v.x < bb) { bb = v.x; bif = v.y; }   // chunks ascending
            }
            int bi = (int)bif;
            if (hi == 0)
                out_codes[((size_t)b * NQ + q) * TT + t0 + t] = bif;
            float ziv = sm.zi[hi][t];
            float raw = __ldg(&cbraw[((size_t)q * CS + bi) * CD + hi]);
            float zqv = ziv + (raw - ziv);
            sm.zqs[hi][t] = zqv;
            out_zqs[(((size_t)b * NQ + q) * CD + hi) * TT + t0 + t] = zqv;
        }
        // wait group W (tables for this q's z_o); group C may stay in flight
        if (q < NQ - 1) cp_wait1(); else cp_wait0();
        __syncthreads();

        // ---- z_o (packed) + fused next-q z_i accumulation, or fused zO at q=8 ----
        ull qq[CD];
        {
            #pragma unroll
            for (int c = 0; c < CD; c++) {
                float v = sm.zqs[c][t];
                qq[c] = pk2(v, v);
            }
        }
        const ulonglong2* wt = reinterpret_cast<const ulonglong2*>(&sm.woutT[0]);
        const ulonglong2* wn = reinterpret_cast<const ulonglong2*>(&sm.winTn[0]);
        const float4* ob4 = reinterpret_cast<const float4*>(&sm.ob[0]);
        float* zosb = out_zos + (((size_t)b * NQ + q) * DD) * TT + t0 + t;
        float* resrow = &sm.res[t][0];
        const int dbase = hi * 64;

        if (q < NQ - 1) {
            ull ac01 = 0ull, ac23 = 0ull, ac45 = 0ull, ac67 = 0ull;
            #pragma unroll 2
            for (int i = 0; i < 16; i++) {
                const int d = dbase + 4 * i;
                const int wi = d >> 2;
                ull a01, a23;
                outproj4(wt, wi, qq, a01, a23);
                float4 obv = ob4[wi];
                float z0v, z1v, z2v, z3v;
                upk2(z0v, z1v, a01); upk2(z2v, z3v, a23);
                float zo0 = z0v + obv.x, zo1 = z1v + obv.y;
                float zo2 = z2v + obv.z, zo3 = z3v + obv.w;
                zosb[(size_t)(d + 0) * TT] = zo0;
                zosb[(size_t)(d + 1) * TT] = zo1;
                zosb[(size_t)(d + 2) * TT] = zo2;
                zosb[(size_t)(d + 3) * TT] = zo3;
                float4 rv = *reinterpret_cast<const float4*>(resrow + d);
                float r0 = rv.x - zo0;
                float r1 = rv.y - zo1;
                float r2v= rv.z - zo2;
                float r3 = rv.w - zo3;
                *reinterpret_cast<float4*>(resrow + d) = make_float4(r0, r1, r2v, r3);
                {
                    ull rr = pk2(r0, r0);
                    ulonglong2 na = wn[2 * (d + 0)], nb = wn[2 * (d + 0) + 1];
                    ac01 = fma2(rr, na.x, ac01); ac23 = fma2(rr, na.y, ac23);
                    ac45 = fma2(rr, nb.x, ac45); ac67 = fma2(rr, nb.y, ac67);
                }
                {
                    ull rr = pk2(r1, r1);
                    ulonglong2 na = wn[2 * (d + 1)], nb = wn[2 * (d + 1) + 1];
                    ac01 = fma2(rr, na.x, ac01); ac23 = fma2(rr, na.y, ac23);
                    ac45 = fma2(rr, nb.x, ac45); ac67 = fma2(rr, nb.y, ac67);
                }
                {
                    ull rr = pk2(r2v, r2v);
                    ulonglong2 na = wn[2 * (d + 2)], nb = wn[2 * (d + 2) + 1];
                    ac01 = fma2(rr, na.x, ac01); ac23 = fma2(rr, na.y, ac23);
                    ac45 = fma2(rr, nb.x, ac45); ac67 = fma2(rr, nb.y, ac67);
                }
                {
                    ull rr = pk2(r3, r3);
                    ulonglong2 na = wn[2 * (d + 3)], nb = wn[2 * (d + 3) + 1];
                    ac01 = fma2(rr, na.x, ac01); ac23 = fma2(rr, na.y, ac23);
                    ac45 = fma2(rr, nb.x, ac45); ac67 = fma2(rr, nb.y, ac67);
                }
            }
            {
                float p0f, p1f, p2f, p3f, p4f, p5f, p6f, p7f;
                upk2(p0f, p1f, ac01); upk2(p2f, p3f, ac23);
                upk2(p4f, p5f, ac45); upk2(p6f, p7f, ac67);
                sm.u.part[0][hi][t] = p0f; sm.u.part[1][hi][t] = p1f;
                sm.u.part[2][hi][t] = p2f; sm.u.part[3][hi][t] = p3f;
                sm.u.part[4][hi][t] = p4f; sm.u.part[5][hi][t] = p5f;
                sm.u.part[6][hi][t] = p6f; sm.u.part[7][hi][t] = p7f;
            }
            __syncthreads();
            // ---- reduce partials -> zi for q+1  (c=hi, t) ----
            {
                float s = sm.u.part[hi][0][t];
                #pragma unroll
                for (int dg = 1; dg < 8; dg++) s += sm.u.part[hi][dg][t];
                float ziv = s + sm.ib_all[(q + 1) * CD + hi];
                sm.zi[hi][t] = ziv;
                out_zis[(((size_t)b * NQ + (q + 1)) * CD + hi) * TT + t0 + t] = ziv;
            }
        } else {
            // final quantizer: fuse zO = z - res_final
            const float* zsrc = zb + t;
            float* zOb = out_zO + (size_t)b * DD * TT + t0 + t;
            #pragma unroll 2
            for (int i = 0; i < 16; i++) {
                const int d = dbase + 4 * i;
                const int wi = d >> 2;
                ull a01, a23;
                outproj4(wt, wi, qq, a01, a23);
                float4 obv = ob4[wi];
                float z0v, z1v, z2v, z3v;
                upk2(z0v, z1v, a01); upk2(z2v, z3v, a23);
                float zo0 = z0v + obv.x, zo1 = z1v + obv.y;
                float zo2 = z2v + obv.z, zo3 = z3v + obv.w;
                zosb[(size_t)(d + 0) * TT] = zo0;
                zosb[(size_t)(d + 1) * TT] = zo1;
                zosb[(size_t)(d + 2) * TT] = zo2;
                zosb[(size_t)(d + 3) * TT] = zo3;
                float4 rv = *reinterpret_cast<const float4*>(resrow + d);
                float r0 = rv.x - zo0;
                float r1 = rv.y - zo1;
                float r2v= rv.z - zo2;
                float r3 = rv.w - zo3;
                zOb[(size_t)(d + 0) * TT] = zsrc[(size_t)(d + 0) * TT] - r0;
                zOb[(size_t)(d + 1) * TT] = zsrc[(size_t)(d + 1) * TT] - r1;
                zOb[(size_t)(d + 2) * TT] = zsrc[(size_t)(d + 2) * TT] - r2v;
                zOb[(size_t)(d + 3) * TT] = zsrc[(size_t)(d + 3) * TT] - r3;
            }
        }
    }
}

extern "C" void kernel_launch(void* const* d_in, const int* in_sizes, int n_in,
                              void* d_out, int out_size) {
    const float* z    = (const float*)d_in[0];
    const float* in_v = (const float*)d_in[1];
    const float* in_g = (const float*)d_in[2];
    const float* in_b = (const float*)d_in[3];
    const float* out_v= (const float*)d_in[4];
    const float* out_g= (const float*)d_in[5];
    const float* out_b= (const float*)d_in[6];
    const float* cb   = (const float*)d_in[7];
    float* out = (float*)d_out;

    rvq_precompute<<<NQ, 256>>>(in_v, in_g, out_v, out_g, cb);

    cudaFuncSetAttribute(rvq_kernel, cudaFuncAttributeMaxDynamicSharedMemorySize,
                         (int)sizeof(SMem));
    dim3 grid(TT / TTILE, BB);
    rvq_kernel<<<grid, NTHREADS, sizeof(SMem)>>>(z, in_b, out_b, cb, out);
}

// round 17
// speedup vs baseline: 1.5451x; 1.5451x over previous
#include <cuda_runtime.h>
#include <math.h>
#include <float.h>
#include <stdint.h>

#define BB 16
#define DD 512
#define TT 2048
#define NQ 9
#define CS 1024
#define CD 8
#define TTILE 64
#define NTHREADS 512

typedef unsigned long long ull;

__device__ __forceinline__ ull pk2(float lo, float hi) {
    ull r; asm("mov.b64 %0,{%1,%2};" : "=l"(r) : "f"(lo), "f"(hi)); return r;
}
__device__ __forceinline__ void upk2(float& lo, float& hi, ull v) {
    asm("mov.b64 {%0,%1},%2;" : "=f"(lo), "=f"(hi) : "l"(v));
}
__device__ __forceinline__ ull fma2(ull a, ull b, ull c) {
    ull d; asm("fma.rn.f32x2 %0,%1,%2,%3;" : "=l"(d) : "l"(a), "l"(b), "l"(c)); return d;
}
__device__ __forceinline__ ull mul2(ull a, ull b) {
    ull d; asm("mul.rn.f32x2 %0,%1,%2;" : "=l"(d) : "l"(a), "l"(b)); return d;
}

// ---------------- precomputed (normalized) parameter scratch ----------------
__device__ float g_win[NQ * CD * DD];    // weight-normed in_proj, c-major (q=0 standalone)
__device__ float g_winT[NQ * DD * CD];   // weight-normed in_proj, d-major (fused path)
__device__ float g_woutT[NQ * CD * DD];  // weight-normed out_proj TRANSPOSED (q, c, d)
__device__ float g_cbn[NQ * CS * CD];    // l2-normalized codebook (linear layout)
__device__ float g_csq[NQ * CS];         // sum(c_norm^2) per code

__global__ void rvq_precompute(const float* __restrict__ iv, const float* __restrict__ ig,
                               const float* __restrict__ ov, const float* __restrict__ og,
                               const float* __restrict__ cb) {
    int q = blockIdx.x;
    int tid = threadIdx.x;           // 256 threads
    int wid = tid >> 5, lane = tid & 31;

    if (wid < CD) {
        int c = wid;
        const float* v = iv + ((size_t)q * CD + c) * DD;
        float ss = 0.f;
        for (int d = lane; d < DD; d += 32) { float x = v[d]; ss = fmaf(x, x, ss); }
        #pragma unroll
        for (int o = 16; o > 0; o >>= 1) ss += __shfl_xor_sync(0xffffffffu, ss, o);
        float nrm = __fsqrt_rn(ss);
        float g = ig[q * CD + c];
        for (int d = lane; d < DD; d += 32) {
            float w = __fdiv_rn(g * v[d], nrm);
            g_win[((size_t)q * CD + c) * DD + d] = w;
            g_winT[((size_t)q * DD + d) * CD + c] = w;
        }
    }
    for (int r = tid; r < DD; r += 256) {
        const float* v = ov + ((size_t)q * DD + r) * CD;
        float ss = 0.f;
        #pragma unroll
        for (int c = 0; c < CD; c++) { float x = v[c]; ss = fmaf(x, x, ss); }
        float nrm = __fsqrt_rn(ss);
        float g = og[q * DD + r];
        #pragma unroll
        for (int c = 0; c < CD; c++)
            g_woutT[((size_t)q * CD + c) * DD + r] = __fdiv_rn(g * v[c], nrm);
    }
    for (int s = tid; s < CS; s += 256) {
        const float* v = cb + ((size_t)q * CS + s) * CD;
        float ss = 0.f;
        #pragma unroll
        for (int c = 0; c < CD; c++) { float x = v[c]; ss = fmaf(x, x, ss); }
        float den = fmaxf(__fsqrt_rn(ss), 1e-12f);
        float cs2 = 0.f;
        #pragma unroll
        for (int c = 0; c < CD; c++) {
            float cn = __fdiv_rn(v[c], den);
            g_cbn[((size_t)q * CS + s) * CD + c] = cn;
            cs2 = fmaf(cn, cn, cs2);
        }
        g_csq[q * CS + s] = cs2;
    }
}

// ---------------- async copy helpers ----------------
__device__ __forceinline__ void cp16(void* dst, const void* src) {
    uint32_t d = (uint32_t)__cvta_generic_to_shared(dst);
    asm volatile("cp.async.cg.shared.global [%0], [%1], 16;" :: "r"(d), "l"(src));
}
__device__ __forceinline__ void cp_commit() {
    asm volatile("cp.async.commit_group;" ::: "memory");
}
__device__ __forceinline__ void cp_wait0() {
    asm volatile("cp.async.wait_group 0;" ::: "memory");
}
__device__ __forceinline__ void cp_wait1() {
    asm volatile("cp.async.wait_group 1;" ::: "memory");
}

// ---------------- main fused RVQ kernel ----------------
struct SMem {
    float4 cbn4[CS * 2];          // 32768  normalized codebook (async group C)
    float  res[DD][TTILE];        // 131072 residual tile
    float4 winTn[DD * 2];         // 16384  next-q in_proj, d-major (async group W)
    float  woutT[CD * DD];        // 16384  out_proj c-major (async; pre-loop: win[0])
    float4 csq4[CS / 4];          // 4096   (async group C)
    float  ob[DD];                // 2048   (async group W)
    float  zi[CD][TTILE];         // 2048
    float  zqs[CD][TTILE];        // 2048
    union {                       // 16384 (disjoint windows: NN->z_q vs z_o->reduce)
        float2 red[16][TTILE];    // (dist, idx-as-float) per chunk
        float  part[CD][8][TTILE];
    } u;
    float ib_all[NQ * CD];        // 288
};  // 223520 B

// packed out-projection for 4 consecutive d (bit-identical per-lane chain)
__device__ __forceinline__ void outproj4(const ulonglong2* wt, int wi,
                                         const ull* qq, ull& a01, ull& a23) {
    ulonglong2 wc = wt[wi];
    a01 = mul2(qq[0], wc.x);  a23 = mul2(qq[0], wc.y);
    #pragma unroll
    for (int c = 1; c < CD; c++) {
        wc = wt[c * (DD / 4) + wi];
        a01 = fma2(qq[c], wc.x, a01);
        a23 = fma2(qq[c], wc.y, a23);
    }
}

__global__ void __launch_bounds__(NTHREADS, 1)
rvq_kernel(const float* __restrict__ z,
           const float* __restrict__ ib_g,
           const float* __restrict__ ob_g,
           const float* __restrict__ cbraw,
           float* __restrict__ out) {
    extern __shared__ unsigned char smraw[];
    SMem& sm = *reinterpret_cast<SMem*>(smraw);

    const int tid = threadIdx.x;
    const int b = blockIdx.y;
    const int t0 = blockIdx.x * TTILE;

    float* out_codes = out;
    float* out_zO  = out + (size_t)BB * NQ * TT;
    float* out_zis = out_zO + (size_t)BB * DD * TT;
    float* out_zqs = out_zis + (size_t)BB * NQ * CD * TT;
    float* out_zos = out_zqs + (size_t)BB * NQ * CD * TT;

    // ---- async prefetch: group Wpre = win[0]; group C0 = cbn/csq(q=0) ----
    {
        const float4* s1 = reinterpret_cast<const float4*>(g_win);
        float4* d1 = reinterpret_cast<float4*>(&sm.woutT[0]);
        for (int i = tid; i < CD * DD / 4; i += NTHREADS) cp16(&d1[i], &s1[i]);
        cp_commit();   // group Wpre
        const float4* s3 = reinterpret_cast<const float4*>(g_cbn);
        for (int i = tid; i < CS * 2; i += NTHREADS) cp16(&sm.cbn4[i], &s3[i]);
        const float4* s4 = reinterpret_cast<const float4*>(g_csq);
        for (int i = tid; i < CS / 4; i += NTHREADS) cp16(&sm.csq4[i], &s4[i]);
        cp_commit();   // group C0 (caught by loop-top cp_wait0 at q=0)
    }

    // ---- load residual tile (vectorized, R15 layout) ----
    const float* zb = z + (size_t)b * DD * TT + t0;
    {
        float4* res4 = reinterpret_cast<float4*>(&sm.res[0][0]);
        for (int f = tid; f < DD * (TTILE / 4); f += NTHREADS) {
            int d = f >> 4, j = f & 15;
            res4[f] = reinterpret_cast<const float4*>(zb + (size_t)d * TT)[j];
        }
        if (tid < NQ * CD) sm.ib_all[tid] = ib_g[tid];
    }
    cp_wait1();        // Wpre (win0) landed; C0 still in flight
    __syncthreads();

    const int t  = tid & (TTILE - 1);   // 0..63
    const int hi = tid >> 6;            // 0..7 (c / d-group)
    const int ch = tid >> 5;            // 0..15 NN chunk of 64 codes
    const int tp = tid & 31;            // NN t-pair: t = 2tp, 2tp+1

    // ---- standalone z_i for q=0  (thread = (c=hi, t)) ----
    {
        const float4* wr4 = reinterpret_cast<const float4*>(&sm.woutT[hi * DD]);
        float a0 = 0.f, a1 = 0.f, a2 = 0.f, a3 = 0.f;
        #pragma unroll 4
        for (int i = 0; i < DD / 4; i++) {
            float4 w = wr4[i];
            int d = 4 * i;
            a0 = fmaf(w.x, sm.res[d + 0][t], a0);
            a1 = fmaf(w.y, sm.res[d + 1][t], a1);
            a2 = fmaf(w.z, sm.res[d + 2][t], a2);
            a3 = fmaf(w.w, sm.res[d + 3][t], a3);
        }
        float ziv = ((a0 + a1) + (a2 + a3)) + sm.ib_all[hi];
        sm.zi[hi][t] = ziv;
        out_zis[(((size_t)b * NQ + 0) * CD + hi) * TT + t0 + t] = ziv;
    }

    for (int q = 0; q < NQ; q++) {
        cp_wait0();        // C group (codebook for this q) landed
        __syncthreads();   // zi ready; prev z_o table reads done; prefetch visible

        // ---- async stage group W: woutT(q), ob(q), winT(q+1) — waited before z_o ----
        {
            const float4* s2 = reinterpret_cast<const float4*>(g_woutT + (size_t)q * CD * DD);
            float4* d2 = reinterpret_cast<float4*>(&sm.woutT[0]);
            for (int i = tid; i < CD * DD / 4; i += NTHREADS) cp16(&d2[i], &s2[i]);
            const float4* s5 = reinterpret_cast<const float4*>(ob_g + (size_t)q * DD);
            float4* d5 = reinterpret_cast<float4*>(&sm.ob[0]);
            for (int i = tid; i < DD / 4; i += NTHREADS) cp16(&d5[i], &s5[i]);
            if (q < NQ - 1) {
                const float4* s6 = reinterpret_cast<const float4*>(
                    g_winT + (size_t)(q + 1) * DD * CD);
                for (int i = tid; i < DD * 2; i += NTHREADS) cp16(&sm.winTn[i], &s6[i]);
            }
            cp_commit();   // group W
        }

        // ---- NN search: thread = (chunk ch of 64 codes, 2 t-columns) ----
        {
            const int ta = 2 * tp, tb = 2 * tp + 1;
            float za0 = sm.zi[0][ta], za1 = sm.zi[1][ta], za2 = sm.zi[2][ta], za3 = sm.zi[3][ta];
            float za4 = sm.zi[4][ta], za5 = sm.zi[5][ta], za6 = sm.zi[6][ta], za7 = sm.zi[7][ta];
            float zb0 = sm.zi[0][tb], zb1 = sm.zi[1][tb], zb2 = sm.zi[2][tb], zb3 = sm.zi[3][tb];
            float zb4 = sm.zi[4][tb], zb5 = sm.zi[5][tb], zb6 = sm.zi[6][tb], zb7 = sm.zi[7][tb];
            float sa = za0 * za0;
            sa = fmaf(za1, za1, sa); sa = fmaf(za2, za2, sa); sa = fmaf(za3, za3, sa);
            sa = fmaf(za4, za4, sa); sa = fmaf(za5, za5, sa); sa = fmaf(za6, za6, sa);
            sa = fmaf(za7, za7, sa);
            float sb = zb0 * zb0;
            sb = fmaf(zb1, zb1, sb); sb = fmaf(zb2, zb2, sb); sb = fmaf(zb3, zb3, sb);
            sb = fmaf(zb4, zb4, sb); sb = fmaf(zb5, zb5, sb); sb = fmaf(zb6, zb6, sb);
            sb = fmaf(zb7, zb7, sb);
            float dena = fmaxf(__fsqrt_rn(sa), 1e-12f);
            float denb = fmaxf(__fsqrt_rn(sb), 1e-12f);
            float ea0 = __fdiv_rn(za0, dena), ea1 = __fdiv_rn(za1, dena);
            float ea2 = __fdiv_rn(za2, dena), ea3 = __fdiv_rn(za3, dena);
            float ea4 = __fdiv_rn(za4, dena), ea5 = __fdiv_rn(za5, dena);
            float ea6 = __fdiv_rn(za6, dena), ea7 = __fdiv_rn(za7, dena);
            float eb0 = __fdiv_rn(zb0, denb), eb1 = __fdiv_rn(zb1, denb);
            float eb2 = __fdiv_rn(zb2, denb), eb3 = __fdiv_rn(zb3, denb);
            float eb4 = __fdiv_rn(zb4, denb), eb5 = __fdiv_rn(zb5, denb);
            float eb6 = __fdiv_rn(zb6, denb), eb7 = __fdiv_rn(zb7, denb);
            float eqa = ea0 * ea0;
            eqa = fmaf(ea1, ea1, eqa); eqa = fmaf(ea2, ea2, eqa); eqa = fmaf(ea3, ea3, eqa);
            eqa = fmaf(ea4, ea4, eqa); eqa = fmaf(ea5, ea5, eqa); eqa = fmaf(ea6, ea6, eqa);
            eqa = fmaf(ea7, ea7, eqa);
            float eqb = eb0 * eb0;
            eqb = fmaf(eb1, eb1, eqb); eqb = fmaf(eb2, eb2, eqb); eqb = fmaf(eb3, eb3, eqb);
            eqb = fmaf(eb4, eb4, eqb); eqb = fmaf(eb5, eb5, eqb); eqb = fmaf(eb6, eb6, eqb);
            eqb = fmaf(eb7, eb7, eqb);

            // channel-pair packed encodings (tree-sum dot; rounding validated R2/R14)
            ull pa0 = pk2(ea0, ea1), pa1 = pk2(ea2, ea3);
            ull pa2 = pk2(ea4, ea5), pa3 = pk2(ea6, ea7);
            ull pb0 = pk2(eb0, eb1), pb1 = pk2(eb2, eb3);
            ull pb2 = pk2(eb4, eb5), pb3 = pk2(eb6, eb7);

            const ulonglong2* cbp = reinterpret_cast<const ulonglong2*>(sm.cbn4);
            const float* csqs = reinterpret_cast<const float*>(sm.csq4);
            const int s0 = ch * 64;
            float bA0 = FLT_MAX, bA1 = FLT_MAX, bB0 = FLT_MAX, bB1 = FLT_MAX;
            int   iA0 = 0, iA1 = 0, iB0 = 0, iB1 = 0;
            #pragma unroll 4
            for (int s = s0; s < s0 + 64; s += 2) {
                ulonglong2 uA0 = cbp[2 * s],     uA1 = cbp[2 * s + 1];
                ulonglong2 uB0 = cbp[2 * s + 2], uB1 = cbp[2 * s + 3];
                float2 csv = *reinterpret_cast<const float2*>(csqs + s);
                ull tAa = fma2(pa0, uA0.x, fma2(pa1, uA0.y, fma2(pa2, uA1.x, mul2(pa3, uA1.y))));
                ull tAb = fma2(pb0, uA0.x, fma2(pb1, uA0.y, fma2(pb2, uA1.x, mul2(pb3, uA1.y))));
                ull tBa = fma2(pa0, uB0.x, fma2(pa1, uB0.y, fma2(pa2, uB1.x, mul2(pa3, uB1.y))));
                ull tBb = fma2(pb0, uB0.x, fma2(pb1, uB0.y, fma2(pb2, uB1.x, mul2(pb3, uB1.y))));
                float lo, hi2;
                upk2(lo, hi2, tAa); float dAa = fmaf(-2.0f, lo + hi2, eqa) + csv.x;
                upk2(lo, hi2, tAb); float dAb = fmaf(-2.0f, lo + hi2, eqb) + csv.x;
                upk2(lo, hi2, tBa); float dBa = fmaf(-2.0f, lo + hi2, eqa) + csv.y;
                upk2(lo, hi2, tBb); float dBb = fmaf(-2.0f, lo + hi2, eqb) + csv.y;
                if (dAa < bA0) { bA0 = dAa; iA0 = s; }
                if (dAb < bA1) { bA1 = dAb; iA1 = s; }
                if (dBa < bB0) { bB0 = dBa; iB0 = s + 1; }
                if (dBb < bB1) { bB1 = dBb; iB1 = s + 1; }
            }
            // merge even/odd chains, exact first-index tie-break
            if (bB0 < bA0 || (bB0 == bA0 && iB0 < iA0)) { bA0 = bB0; iA0 = iB0; }
            if (bB1 < bA1 || (bB1 == bA1 && iB1 < iA1)) { bA1 = bB1; iA1 = iB1; }
            sm.u.red[ch][ta] = make_float2(bA0, (float)iA0);
            sm.u.red[ch][tb] = make_float2(bA1, (float)iA1);
        }
        __syncthreads();

        // ---- issue group C: prefetch next-q codebook (flies through z_q + z_o) ----
        if (q < NQ - 1) {
            const float4* srcC = reinterpret_cast<const float4*>(
                g_cbn + (size_t)(q + 1) * CS * CD);
            for (int i = tid; i < CS * 2; i += NTHREADS) cp16(&sm.cbn4[i], &srcC[i]);
            const float4* srcQ = reinterpret_cast<const float4*>(
                g_csq + (size_t)(q + 1) * CS);
            for (int i = tid; i < CS / 4; i += NTHREADS) cp16(&sm.csq4[i], &srcQ[i]);
            cp_commit();   // group C
        }

        // ---- z_q: redundant argmin merge (16 chunks) + straight-through (c=hi, t) ----
        {
            float2 v0 = sm.u.red[0][t];
            float bb = v0.x; float bif = v0.y;
            #pragma unroll
            for (int g = 1; g < 16; g++) {
                float2 v = sm.u.red[g][t];
                if (v.x < bb) { bb = v.x; bif = v.y; }   // chunks ascending
            }
            int bi = (int)bif;
            if (hi == 0)
                out_codes[((size_t)b * NQ + q) * TT + t0 + t] = bif;
            float ziv = sm.zi[hi][t];
            float raw = __ldg(&cbraw[((size_t)q * CS + bi) * CD + hi]);
            float zqv = ziv + (raw - ziv);
            sm.zqs[hi][t] = zqv;
            out_zqs[(((size_t)b * NQ + q) * CD + hi) * TT + t0 + t] = zqv;
        }
        // wait group W (tables for this q's z_o); group C may stay in flight
        if (q < NQ - 1) cp_wait1(); else cp_wait0();
        __syncthreads();

        // ---- z_o (packed) + fused next-q z_i accumulation, or fused zO at q=8 ----
        ull qq[CD];
        {
            #pragma unroll
            for (int c = 0; c < CD; c++) {
                float v = sm.zqs[c][t];
                qq[c] = pk2(v, v);
            }
        }
        const ulonglong2* wt = reinterpret_cast<const ulonglong2*>(&sm.woutT[0]);
        const ulonglong2* wn = reinterpret_cast<const ulonglong2*>(&sm.winTn[0]);
        const float4* ob4 = reinterpret_cast<const float4*>(&sm.ob[0]);
        float* zosb = out_zos + (((size_t)b * NQ + q) * DD) * TT + t0 + t;
        const int dbase = hi * 64;

        if (q < NQ - 1) {
            ull ac01 = 0ull, ac23 = 0ull, ac45 = 0ull, ac67 = 0ull;
            #pragma unroll 2
            for (int i = 0; i < 16; i++) {
                const int d = dbase + 4 * i;
                const int wi = d >> 2;
                ull a01, a23;
                outproj4(wt, wi, qq, a01, a23);
                float4 obv = ob4[wi];
                float z0v, z1v, z2v, z3v;
                upk2(z0v, z1v, a01); upk2(z2v, z3v, a23);
                float zo0 = z0v + obv.x, zo1 = z1v + obv.y;
                float zo2 = z2v + obv.z, zo3 = z3v + obv.w;
                zosb[(size_t)(d + 0) * TT] = zo0;
                zosb[(size_t)(d + 1) * TT] = zo1;
                zosb[(size_t)(d + 2) * TT] = zo2;
                zosb[(size_t)(d + 3) * TT] = zo3;
                float r0 = sm.res[d + 0][t] - zo0; sm.res[d + 0][t] = r0;
                float r1 = sm.res[d + 1][t] - zo1; sm.res[d + 1][t] = r1;
                float r2v= sm.res[d + 2][t] - zo2; sm.res[d + 2][t] = r2v;
                float r3 = sm.res[d + 3][t] - zo3; sm.res[d + 3][t] = r3;
                {
                    ull rr = pk2(r0, r0);
                    ulonglong2 na = wn[2 * (d + 0)], nb = wn[2 * (d + 0) + 1];
                    ac01 = fma2(rr, na.x, ac01); ac23 = fma2(rr, na.y, ac23);
                    ac45 = fma2(rr, nb.x, ac45); ac67 = fma2(rr, nb.y, ac67);
                }
                {
                    ull rr = pk2(r1, r1);
                    ulonglong2 na = wn[2 * (d + 1)], nb = wn[2 * (d + 1) + 1];
                    ac01 = fma2(rr, na.x, ac01); ac23 = fma2(rr, na.y, ac23);
                    ac45 = fma2(rr, nb.x, ac45); ac67 = fma2(rr, nb.y, ac67);
                }
                {
                    ull rr = pk2(r2v, r2v);
                    ulonglong2 na = wn[2 * (d + 2)], nb = wn[2 * (d + 2) + 1];
                    ac01 = fma2(rr, na.x, ac01); ac23 = fma2(rr, na.y, ac23);
                    ac45 = fma2(rr, nb.x, ac45); ac67 = fma2(rr, nb.y, ac67);
                }
                {
                    ull rr = pk2(r3, r3);
                    ulonglong2 na = wn[2 * (d + 3)], nb = wn[2 * (d + 3) + 1];
                    ac01 = fma2(rr, na.x, ac01); ac23 = fma2(rr, na.y, ac23);
                    ac45 = fma2(rr, nb.x, ac45); ac67 = fma2(rr, nb.y, ac67);
                }
            }
            {
                float p0f, p1f, p2f, p3f, p4f, p5f, p6f, p7f;
                upk2(p0f, p1f, ac01); upk2(p2f, p3f, ac23);
                upk2(p4f, p5f, ac45); upk2(p6f, p7f, ac67);
                sm.u.part[0][hi][t] = p0f; sm.u.part[1][hi][t] = p1f;
                sm.u.part[2][hi][t] = p2f; sm.u.part[3][hi][t] = p3f;
                sm.u.part[4][hi][t] = p4f; sm.u.part[5][hi][t] = p5f;
                sm.u.part[6][hi][t] = p6f; sm.u.part[7][hi][t] = p7f;
            }
            __syncthreads();
            // ---- reduce partials -> zi for q+1  (c=hi, t) ----
            {
                float s = sm.u.part[hi][0][t];
                #pragma unroll
                for (int dg = 1; dg < 8; dg++) s += sm.u.part[hi][dg][t];
                float ziv = s + sm.ib_all[(q + 1) * CD + hi];
                sm.zi[hi][t] = ziv;
                out_zis[(((size_t)b * NQ + (q + 1)) * CD + hi) * TT + t0 + t] = ziv;
            }
        } else {
            // final quantizer: fuse zO = z - res_final
            const float* zsrc = zb + t;
            float* zOb = out_zO + (size_t)b * DD * TT + t0 + t;
            #pragma unroll 2
            for (int i = 0; i < 16; i++) {
                const int d = dbase + 4 * i;
                const int wi = d >> 2;
                ull a01, a23;
                outproj4(wt, wi, qq, a01, a23);
                float4 obv = ob4[wi];
                float z0v, z1v, z2v, z3v;
                upk2(z0v, z1v, a01); upk2(z2v, z3v, a23);
                float zo0 = z0v + obv.x, zo1 = z1v + obv.y;
                float zo2 = z2v + obv.z, zo3 = z3v + obv.w;
                zosb[(size_t)(d + 0) * TT] = zo0;
                zosb[(size_t)(d + 1) * TT] = zo1;
                zosb[(size_t)(d + 2) * TT] = zo2;
                zosb[(size_t)(d + 3) * TT] = zo3;
                float r0 = sm.res[d + 0][t] - zo0;
                float r1 = sm.res[d + 1][t] - zo1;
                float r2v= sm.res[d + 2][t] - zo2;
                float r3 = sm.res[d + 3][t] - zo3;
                zOb[(size_t)(d + 0) * TT] = zsrc[(size_t)(d + 0) * TT] - r0;
                zOb[(size_t)(d + 1) * TT] = zsrc[(size_t)(d + 1) * TT] - r1;
                zOb[(size_t)(d + 2) * TT] = zsrc[(size_t)(d + 2) * TT] - r2v;
                zOb[(size_t)(d + 3) * TT] = zsrc[(size_t)(d + 3) * TT] - r3;
            }
        }
    }
}

extern "C" void kernel_launch(void* const* d_in, const int* in_sizes, int n_in,
                              void* d_out, int out_size) {
    const float* z    = (const float*)d_in[0];
    const float* in_v = (const float*)d_in[1];
    const float* in_g = (const float*)d_in[2];
    const float* in_b = (const float*)d_in[3];
    const float* out_v= (const float*)d_in[4];
    const float* out_g= (const float*)d_in[5];
    const float* out_b= (const float*)d_in[6];
    const float* cb   = (const float*)d_in[7];
    float* out = (float*)d_out;

    rvq_precompute<<<NQ, 256>>>(in_v, in_g, out_v, out_g, cb);

    cudaFuncSetAttribute(rvq_kernel, cudaFuncAttributeMaxDynamicSharedMemorySize,
                         (int)sizeof(SMem));
    dim3 grid(TT / TTILE, BB);
    rvq_kernel<<<grid, NTHREADS, sizeof(SMem)>>>(z, in_b, out_b, cb, out);
}